// round 6
// baseline (speedup 1.0000x reference)
#include <cuda_runtime.h>
#include <cuda_bf16.h>
#include <cstdint>

// Problem constants
#define M_ROWS 4096
#define K_DIM  256
#define NN     16384
#define KTOP   1638

// GEMM tiling
#define TR 128              // rows per tile
#define TC 128              // cols per tile
#define XS_STRIDE 132       // floats; 132*4=528=33*16 -> LDS.128 stays 16B-aligned
#define OS_STRIDE 129       // 129 % 32 == 1 -> conflict-free column stores
#define GEMM_SMEM ((K_DIM * XS_STRIDE + TR * OS_STRIDE) * 4)

#define SLOTS 64            // per-column CSC capacity (max nnz ~48 for 10% of 256)

// ---------------------------------------------------------------------------
// Scratch: per-column packed CSC of W: g_pack[n*SLOTS + j] = (w, k-as-bits)
// Contiguous per column -> one coalesced LDG.64 preloads 32 pairs into a warp.
// ---------------------------------------------------------------------------
__device__ float2 g_pack[(size_t)NN * SLOTS];   // 8.4 MB
__device__ int    g_cnt[NN];

// ---------------------------------------------------------------------------
// Kernel 1: build packed CSC. One thread per output column; W reads coalesced
// across adjacent n. Zero weights dropped (never changes the sum).
// ---------------------------------------------------------------------------
__global__ void __launch_bounds__(128) build_pack_kernel(const float* __restrict__ W) {
    const int n = blockIdx.x * blockDim.x + threadIdx.x;
    if (n >= NN) return;
    int c = 0;
#pragma unroll 8
    for (int k = 0; k < K_DIM; ++k) {
        const float w = W[(size_t)k * NN + n];
        if (w != 0.0f) {
            if (c < SLOTS) g_pack[(size_t)n * SLOTS + c] = make_float2(w, __int_as_float(k));
            ++c;
        }
    }
    g_cnt[n] = (c < SLOTS) ? c : SLOTS;
}

// ---------------------------------------------------------------------------
// Kernel 2: sparse GEMM  out = relu(x @ W + bias), dense output.
// Tile 128 rows x 128 cols, 256 threads / 8 warps; warp owns 16 columns
// sequentially; lane owns 4 consecutive rows (float4 from smem x-tile).
// Column pair-lists preloaded into lane registers (coalesced LDG, prefetched
// one column ahead), broadcast in-loop via shfl. Inner loop runs in unroll-8
// chunks over the zero-padded count: 8 independent LDS.128 in flight.
// ---------------------------------------------------------------------------
__global__ void __launch_bounds__(256, 1) gemm_kernel(
    const float* __restrict__ x,
    const float* __restrict__ bias,
    float* __restrict__ out)
{
    extern __shared__ float sm[];
    float* xs = sm;                          // [K_DIM][XS_STRIDE]
    float* os = sm + K_DIM * XS_STRIDE;      // [TR][OS_STRIDE]

    const int row0 = blockIdx.y * TR;
    const int col0 = blockIdx.x * TC;

    // fill x tile transposed: xs[k][r]  (gmem coalesced)
    for (int u = threadIdx.x; u < TR * K_DIM; u += 256) {
        const int r = u >> 8;                // 0..127
        const int k = u & 255;               // 0..255
        xs[k * XS_STRIDE + r] = x[(size_t)(row0 + r) * K_DIM + k];
    }
    __syncthreads();

    const int warp  = threadIdx.x >> 5;
    const int lane  = threadIdx.x & 31;
    const int rbase = lane << 2;

    // preload column 0 of this warp
    int n = col0 + (warp << 4);
    int cnt = g_cnt[n];
    float bn = __ldg(bias + n);
    float2 pa = make_float2(0.f, 0.f), pb = make_float2(0.f, 0.f);
    if (lane < cnt)      pa = g_pack[(size_t)n * SLOTS + lane];
    if (32 + lane < cnt) pb = g_pack[(size_t)n * SLOTS + 32 + lane];

    for (int cc = 0; cc < 16; ++cc) {
        const float2 pa_c = pa, pb_c = pb;
        const int cnt_c = cnt;
        const float b = bn;
        const int c = (warp << 4) + cc;

        if (cc < 15) {                        // prefetch next column
            const int n2 = n + 1;
            cnt = g_cnt[n2];
            bn  = __ldg(bias + n2);
            pa = make_float2(0.f, 0.f); pb = make_float2(0.f, 0.f);
            if (lane < cnt)      pa = g_pack[(size_t)n2 * SLOTS + lane];
            if (32 + lane < cnt) pb = g_pack[(size_t)n2 * SLOTS + 32 + lane];
            n = n2;
        }

        float4 acc = make_float4(0.f, 0.f, 0.f, 0.f);
        const int cpad = (cnt_c + 7) & ~7;    // chunks never straddle j=32
        for (int j = 0; j < cpad; j += 8) {
            const float2 s = (j < 32) ? pa_c : pb_c;
            const int base = j & 31;
#pragma unroll
            for (int u = 0; u < 8; ++u) {
                const float w = __shfl_sync(0xffffffffu, s.x, base + u);
                const int   k = __float_as_int(__shfl_sync(0xffffffffu, s.y, base + u));
                const float4 xv = *(const float4*)(xs + k * XS_STRIDE + rbase);
                acc.x = fmaf(xv.x, w, acc.x);
                acc.y = fmaf(xv.y, w, acc.y);
                acc.z = fmaf(xv.z, w, acc.z);
                acc.w = fmaf(xv.w, w, acc.w);
            }
        }

        acc.x = fmaxf(acc.x + b, 0.f);
        acc.y = fmaxf(acc.y + b, 0.f);
        acc.z = fmaxf(acc.z + b, 0.f);
        acc.w = fmaxf(acc.w + b, 0.f);

        os[(rbase + 0) * OS_STRIDE + c] = acc.x;
        os[(rbase + 1) * OS_STRIDE + c] = acc.y;
        os[(rbase + 2) * OS_STRIDE + c] = acc.z;
        os[(rbase + 3) * OS_STRIDE + c] = acc.w;
    }
    __syncthreads();

    // flush tile, scalar + coalesced (consecutive threads -> consecutive cols)
    for (int l = threadIdx.x; l < TR * TC; l += 256) {
        const int r = l >> 7;
        const int c = l & 127;
        out[(size_t)(row0 + r) * NN + col0 + c] = os[r * OS_STRIDE + c];
    }
}

// ---------------------------------------------------------------------------
// Kernel 3: per-row exact top-K (radix select on float bits; relu => all >= 0
// so uint compare is order-preserving). In-place on `out`. Zeros (~50% of a
// row) counted via warp ballot instead of same-address atomics.
// ---------------------------------------------------------------------------
#define SEL_SMEM (NN * 4 + 4096 * 4 + 512 * 4)

__global__ void __launch_bounds__(256) topk_kernel(float* __restrict__ out) {
    extern __shared__ unsigned int smv[];
    unsigned int* v    = smv;                       // [16384]
    int*          hist = (int*)(smv + NN);          // up to 4096 bins
    int*          eqix = (int*)(smv + NN + 4096);   // [512]

    __shared__ int chunksum[256];
    __shared__ int s_b1, s_b2, s_b3, s_krem, s_eqcnt;

    const int t = threadIdx.x;
    const int warp = t >> 5, lane = t & 31;
    float* rp = out + (size_t)blockIdx.x * NN;

    for (int i = t; i < NN / 4; i += 256)
        ((uint4*)v)[i] = ((const uint4*)rp)[i];

    // ---- pass 1: bits [31:23], warp-private 256-bin hists; ballot zeros ----
    for (int i = t; i < 8 * 256; i += 256) hist[i] = 0;
    __syncthreads();
    {
        int* h1 = hist + warp * 256;
        for (int i = t; i < NN; i += 256) {
            const unsigned int u = v[i];
            const unsigned int zm = __ballot_sync(0xffffffffu, u == 0u);
            if (u) atomicAdd(&h1[u >> 23], 1);
            else if ((zm & ((1u << lane) - 1u)) == 0u)   // lowest zero lane
                atomicAdd(&h1[0], __popc(zm));
        }
    }
    __syncthreads();
    {
        int s = 0;
        for (int w = 0; w < 8; ++w) s += hist[w * 256 + t];
        chunksum[t] = s;
    }
    __syncthreads();
    if (t == 0) {
        int kr = KTOP, b = 255;
        for (;; --b) { const int h = chunksum[b]; if (h >= kr) break; kr -= h; }
        s_b1 = b; s_krem = kr;
    }
    __syncthreads();
    const unsigned int b1 = (unsigned int)s_b1;

    // ---- pass 2: bits [22:12] (2048 bins) ----
    for (int i = t; i < 2048; i += 256) hist[i] = 0;
    __syncthreads();
    for (int i = t; i < NN; i += 256) {
        const unsigned int u = v[i];
        if ((u >> 23) == b1) atomicAdd(&hist[(u >> 12) & 2047], 1);
    }
    __syncthreads();
    { int s = 0; for (int k = 0; k < 8; ++k) s += hist[t * 8 + k]; chunksum[t] = s; }
    __syncthreads();
    if (t == 0) {
        int kr = s_krem, c = 255;
        for (;; --c) { const int h = chunksum[c]; if (h >= kr) break; kr -= h; }
        int b = c * 8 + 7;
        for (;; --b) { const int h = hist[b]; if (h >= kr) break; kr -= h; }
        s_b2 = b; s_krem = kr;
    }
    __syncthreads();
    const unsigned int pfx2 = (b1 << 11) | (unsigned int)s_b2;

    // ---- pass 3: bits [11:0] (4096 bins) ----
    for (int i = t; i < 4096; i += 256) hist[i] = 0;
    __syncthreads();
    for (int i = t; i < NN; i += 256) {
        const unsigned int u = v[i];
        if ((u >> 12) == pfx2) atomicAdd(&hist[u & 4095], 1);
    }
    __syncthreads();
    { int s = 0; for (int k = 0; k < 16; ++k) s += hist[t * 16 + k]; chunksum[t] = s; }
    __syncthreads();
    if (t == 0) {
        int kr = s_krem, c = 255;
        for (;; --c) { const int h = chunksum[c]; if (h >= kr) break; kr -= h; }
        int b = c * 16 + 15;
        for (;; --b) { const int h = hist[b]; if (h >= kr) break; kr -= h; }
        s_b3 = b; s_krem = kr;        // kr = # of elements == threshold to KEEP
        s_eqcnt = 0;
    }
    __syncthreads();

    const unsigned int tbits = (pfx2 << 12) | (unsigned int)s_b3;
    const int need = s_krem;
    const int m    = hist[s_b3];
    const bool keep_all_eq = (need >= m) || (m > 512);

    // exact tie ranking (lowest indices first) — rare path
    if (tbits != 0u && !keep_all_eq) {
        for (int i = t; i < NN; i += 256)
            if (v[i] == tbits) { const int p = atomicAdd(&s_eqcnt, 1); eqix[p] = i; }
        __syncthreads();
    }

    // write masked row back
    for (int i = t; i < NN; i += 256) {
        const unsigned int u = v[i];
        float val = 0.0f;
        if (u > tbits) {
            val = __uint_as_float(u);
        } else if (u == tbits && tbits != 0u) {
            if (keep_all_eq) {
                val = __uint_as_float(u);
            } else {
                int rank = 0;
                for (int q = 0; q < m; ++q) rank += (eqix[q] < i);
                if (rank < need) val = __uint_as_float(u);
            }
        }
        rp[i] = val;
    }
}

// ---------------------------------------------------------------------------
// Launch
// ---------------------------------------------------------------------------
extern "C" void kernel_launch(void* const* d_in, const int* in_sizes, int n_in,
                              void* d_out, int out_size)
{
    const float* x = nullptr;
    const float* W = nullptr;
    const float* bias = nullptr;
    for (int i = 0; i < n_in; ++i) {
        if (in_sizes[i] == M_ROWS * K_DIM)      x = (const float*)d_in[i];
        else if (in_sizes[i] == K_DIM * NN)     W = (const float*)d_in[i];
        else if (in_sizes[i] == NN)             bias = (const float*)d_in[i];
    }
    float* out = (float*)d_out;

    cudaFuncSetAttribute(gemm_kernel, cudaFuncAttributeMaxDynamicSharedMemorySize, GEMM_SMEM);
    cudaFuncSetAttribute(topk_kernel, cudaFuncAttributeMaxDynamicSharedMemorySize, SEL_SMEM);

    build_pack_kernel<<<NN / 128, 128>>>(W);

    dim3 ggrid(NN / TC, M_ROWS / TR);        // 128 x 32 = 4096 tiles
    gemm_kernel<<<ggrid, 256, GEMM_SMEM>>>(x, bias, out);

    topk_kernel<<<M_ROWS, 256, SEL_SMEM>>>(out);
}

// round 8
// speedup vs baseline: 1.1254x; 1.1254x over previous
#include <cuda_runtime.h>
#include <cuda_bf16.h>
#include <cstdint>

// Problem constants
#define M_ROWS 4096
#define K_DIM  256
#define NN     16384
#define KTOP   1638

// GEMM tiling
#define TR 128              // rows per tile
#define TC 128              // cols per tile
#define XS_STRIDE 132       // floats; 132*4=528=33*16 -> LDS.128 16B-aligned
#define OS_STRIDE 129       // 129 % 32 == 1 -> conflict-free column stores
#define SLOTS 64            // per-column CSC capacity (binomial(256,0.1) max ~48)

#define PP_OFF   (K_DIM * XS_STRIDE)            // float index of pair tile
#define SCNT_OFF (PP_OFF + SLOTS * TC * 2)      // float index of counts
#define GEMM_SMEM ((SCNT_OFF + TC) * 4)         // 201216 B

// ---------------------------------------------------------------------------
// Scratch: CSC of W, [slot][n] layout (coalesced build writes AND gemm loads)
// pair = (w, k-as-float-bits). Slots >= cnt are zero-filled => inert in FMA.
// ---------------------------------------------------------------------------
__device__ float2 g_pairT[(size_t)SLOTS * NN];   // 8.4 MB
__device__ int    g_cnt[NN];

// ---------------------------------------------------------------------------
// Kernel 0: zero the pair scratch (makes padded slots inert every replay).
// ---------------------------------------------------------------------------
__global__ void __launch_bounds__(256) zero_pairs_kernel() {
    const size_t i = (size_t)blockIdx.x * 256 + threadIdx.x;   // float4 units
    ((float4*)g_pairT)[i] = make_float4(0.f, 0.f, 0.f, 0.f);
}

// ---------------------------------------------------------------------------
// Kernel 1: build CSC. One thread per column; W reads and g_pairT writes are
// both coalesced across adjacent n. Zero weights dropped (sum unchanged).
// ---------------------------------------------------------------------------
__global__ void __launch_bounds__(128) build_pack_kernel(const float* __restrict__ W) {
    const int n = blockIdx.x * blockDim.x + threadIdx.x;
    if (n >= NN) return;
    int c = 0;
#pragma unroll 8
    for (int k = 0; k < K_DIM; ++k) {
        const float w = W[(size_t)k * NN + n];
        if (w != 0.0f) {
            if (c < SLOTS) g_pairT[(size_t)c * NN + n] = make_float2(w, __int_as_float(k));
            ++c;
        }
    }
    g_cnt[n] = (c < SLOTS) ? c : SLOTS;
}

// ---------------------------------------------------------------------------
// Kernel 2: sparse GEMM  out = relu(x @ W + bias), dense output.
// Tile 128 rows x 128 cols, 256 threads / 8 warps; warp owns 16 columns,
// lane owns 4 consecutive rows (float4 from smem x-tile).
// Column pair lists staged in SMEM; in-loop pair reads are warp-uniform
// LDS.64 broadcasts (no shfl, no in-loop LDG). 16 column accumulators are
// kept in registers; the output staging buffer overlays the x-tile.
// ---------------------------------------------------------------------------
__global__ void __launch_bounds__(256, 1) gemm_kernel(
    const float* __restrict__ x,
    const float* __restrict__ bias,
    float* __restrict__ out)
{
    extern __shared__ float sm[];
    float*  xs    = sm;                          // [K_DIM][XS_STRIDE]
    float2* ppair = (float2*)(sm + PP_OFF);      // [SLOTS][TC]
    int*    scnt  = (int*)(sm + SCNT_OFF);       // [TC]

    const int row0 = blockIdx.y * TR;
    const int col0 = blockIdx.x * TC;
    const int tid  = threadIdx.x;

    // fill x tile transposed: xs[k][r]  (gmem coalesced)
    for (int u = tid; u < TR * K_DIM; u += 256) {
        const int r = u >> 8;                // 0..127
        const int k = u & 255;               // 0..255
        xs[k * XS_STRIDE + r] = x[(size_t)(row0 + r) * K_DIM + k];
    }
    // fill pair tile: ppair[s][c] <- g_pairT[s][col0+c]  (LDG.64 coalesced)
    for (int u = tid; u < SLOTS * TC; u += 256) {
        const int s = u >> 7;                // slot
        const int c = u & 127;               // col in tile
        ppair[s * TC + c] = g_pairT[(size_t)s * NN + col0 + c];
    }
    if (tid < TC) scnt[tid] = g_cnt[col0 + tid];
    __syncthreads();

    const int warp  = tid >> 5;
    const int lane  = tid & 31;
    const int rbase = lane << 2;

    float4 acc[16];
#pragma unroll
    for (int cc = 0; cc < 16; ++cc) {
        const int c = (warp << 4) + cc;
        const int cnt = scnt[c];
        const float2* pp = ppair + c;
        float4 a = make_float4(0.f, 0.f, 0.f, 0.f);
        for (int j = 0; j < cnt; j += 8) {   // tail slots are zero => inert
#pragma unroll
            for (int u = 0; u < 8; ++u) {
                const float2 p = pp[(j + u) * TC];              // broadcast
                const int    k = __float_as_int(p.y);
                const float4 xv = *(const float4*)(xs + k * XS_STRIDE + rbase);
                a.x = fmaf(xv.x, p.x, a.x);
                a.y = fmaf(xv.y, p.x, a.y);
                a.z = fmaf(xv.z, p.x, a.z);
                a.w = fmaf(xv.w, p.x, a.w);
            }
        }
        const float b = __ldg(bias + col0 + c);
        a.x = fmaxf(a.x + b, 0.f);
        a.y = fmaxf(a.y + b, 0.f);
        a.z = fmaxf(a.z + b, 0.f);
        a.w = fmaxf(a.w + b, 0.f);
        acc[cc] = a;
    }
    __syncthreads();                         // xs reads done -> reuse as os

    float* os = sm;                          // [TR][OS_STRIDE], overlays xs
#pragma unroll
    for (int cc = 0; cc < 16; ++cc) {
        const int c = (warp << 4) + cc;
        os[(rbase + 0) * OS_STRIDE + c] = acc[cc].x;
        os[(rbase + 1) * OS_STRIDE + c] = acc[cc].y;
        os[(rbase + 2) * OS_STRIDE + c] = acc[cc].z;
        os[(rbase + 3) * OS_STRIDE + c] = acc[cc].w;
    }
    __syncthreads();

    // flush tile, scalar + coalesced (consecutive threads -> consecutive cols)
    for (int l = tid; l < TR * TC; l += 256) {
        const int r = l >> 7;
        const int c = l & 127;
        out[(size_t)(row0 + r) * NN + col0 + c] = os[r * OS_STRIDE + c];
    }
}

// ---------------------------------------------------------------------------
// Kernel 3: per-row exact top-K (radix select on float bits; relu => all >= 0
// so uint compare is order-preserving). In-place on `out`. Zeros (~50% of a
// row) counted via warp ballot instead of same-address atomics.
// ---------------------------------------------------------------------------
#define SEL_SMEM (NN * 4 + 4096 * 4 + 512 * 4)

__global__ void __launch_bounds__(256) topk_kernel(float* __restrict__ out) {
    extern __shared__ unsigned int smv[];
    unsigned int* v    = smv;                       // [16384]
    int*          hist = (int*)(smv + NN);          // up to 4096 bins
    int*          eqix = (int*)(smv + NN + 4096);   // [512]

    __shared__ int chunksum[256];
    __shared__ int s_b1, s_b2, s_b3, s_krem, s_eqcnt;

    const int t = threadIdx.x;
    const int warp = t >> 5, lane = t & 31;
    float* rp = out + (size_t)blockIdx.x * NN;

    for (int i = t; i < NN / 4; i += 256)
        ((uint4*)v)[i] = ((const uint4*)rp)[i];

    // ---- pass 1: bits [31:23], warp-private 256-bin hists; ballot zeros ----
    for (int i = t; i < 8 * 256; i += 256) hist[i] = 0;
    __syncthreads();
    {
        int* h1 = hist + warp * 256;
        for (int i = t; i < NN; i += 256) {
            const unsigned int u = v[i];
            const unsigned int zm = __ballot_sync(0xffffffffu, u == 0u);
            if (u) atomicAdd(&h1[u >> 23], 1);
            else if ((zm & ((1u << lane) - 1u)) == 0u)   // lowest zero lane
                atomicAdd(&h1[0], __popc(zm));
        }
    }
    __syncthreads();
    {
        int s = 0;
        for (int w = 0; w < 8; ++w) s += hist[w * 256 + t];
        chunksum[t] = s;
    }
    __syncthreads();
    if (t == 0) {
        int kr = KTOP, b = 255;
        for (;; --b) { const int h = chunksum[b]; if (h >= kr) break; kr -= h; }
        s_b1 = b; s_krem = kr;
    }
    __syncthreads();
    const unsigned int b1 = (unsigned int)s_b1;

    // ---- pass 2: bits [22:12] (2048 bins) ----
    for (int i = t; i < 2048; i += 256) hist[i] = 0;
    __syncthreads();
    for (int i = t; i < NN; i += 256) {
        const unsigned int u = v[i];
        if ((u >> 23) == b1) atomicAdd(&hist[(u >> 12) & 2047], 1);
    }
    __syncthreads();
    { int s = 0; for (int k = 0; k < 8; ++k) s += hist[t * 8 + k]; chunksum[t] = s; }
    __syncthreads();
    if (t == 0) {
        int kr = s_krem, c = 255;
        for (;; --c) { const int h = chunksum[c]; if (h >= kr) break; kr -= h; }
        int b = c * 8 + 7;
        for (;; --b) { const int h = hist[b]; if (h >= kr) break; kr -= h; }
        s_b2 = b; s_krem = kr;
    }
    __syncthreads();
    const unsigned int pfx2 = (b1 << 11) | (unsigned int)s_b2;

    // ---- pass 3: bits [11:0] (4096 bins) ----
    for (int i = t; i < 4096; i += 256) hist[i] = 0;
    __syncthreads();
    for (int i = t; i < NN; i += 256) {
        const unsigned int u = v[i];
        if ((u >> 12) == pfx2) atomicAdd(&hist[u & 4095], 1);
    }
    __syncthreads();
    { int s = 0; for (int k = 0; k < 16; ++k) s += hist[t * 16 + k]; chunksum[t] = s; }
    __syncthreads();
    if (t == 0) {
        int kr = s_krem, c = 255;
        for (;; --c) { const int h = chunksum[c]; if (h >= kr) break; kr -= h; }
        int b = c * 16 + 15;
        for (;; --b) { const int h = hist[b]; if (h >= kr) break; kr -= h; }
        s_b3 = b; s_krem = kr;        // kr = # of elements == threshold to KEEP
        s_eqcnt = 0;
    }
    __syncthreads();

    const unsigned int tbits = (pfx2 << 12) | (unsigned int)s_b3;
    const int need = s_krem;
    const int m    = hist[s_b3];
    const bool keep_all_eq = (need >= m) || (m > 512);

    // exact tie ranking (lowest indices first) — rare path
    if (tbits != 0u && !keep_all_eq) {
        for (int i = t; i < NN; i += 256)
            if (v[i] == tbits) { const int p = atomicAdd(&s_eqcnt, 1); eqix[p] = i; }
        __syncthreads();
    }

    // write masked row back
    for (int i = t; i < NN; i += 256) {
        const unsigned int u = v[i];
        float val = 0.0f;
        if (u > tbits) {
            val = __uint_as_float(u);
        } else if (u == tbits && tbits != 0u) {
            if (keep_all_eq) {
                val = __uint_as_float(u);
            } else {
                int rank = 0;
                for (int q = 0; q < m; ++q) rank += (eqix[q] < i);
                if (rank < need) val = __uint_as_float(u);
            }
        }
        rp[i] = val;
    }
}

// ---------------------------------------------------------------------------
// Launch
// ---------------------------------------------------------------------------
extern "C" void kernel_launch(void* const* d_in, const int* in_sizes, int n_in,
                              void* d_out, int out_size)
{
    const float* x = nullptr;
    const float* W = nullptr;
    const float* bias = nullptr;
    for (int i = 0; i < n_in; ++i) {
        if (in_sizes[i] == M_ROWS * K_DIM)      x = (const float*)d_in[i];
        else if (in_sizes[i] == K_DIM * NN)     W = (const float*)d_in[i];
        else if (in_sizes[i] == NN)             bias = (const float*)d_in[i];
    }
    float* out = (float*)d_out;

    cudaFuncSetAttribute(gemm_kernel, cudaFuncAttributeMaxDynamicSharedMemorySize, GEMM_SMEM);
    cudaFuncSetAttribute(topk_kernel, cudaFuncAttributeMaxDynamicSharedMemorySize, SEL_SMEM);

    // zero pair scratch: SLOTS*NN float2 = 2*SLOTS*NN floats = SLOTS*NN/2 float4
    zero_pairs_kernel<<<(SLOTS * NN / 2) / 256, 256>>>();
    build_pack_kernel<<<NN / 128, 128>>>(W);

    dim3 ggrid(NN / TC, M_ROWS / TR);        // 128 x 32 = 4096 tiles
    gemm_kernel<<<ggrid, 256, GEMM_SMEM>>>(x, bias, out);

    topk_kernel<<<M_ROWS, 256, SEL_SMEM>>>(out);
}

// round 9
// speedup vs baseline: 1.5953x; 1.4176x over previous
#include <cuda_runtime.h>
#include <cuda_bf16.h>
#include <cstdint>

// Problem constants
#define M_ROWS 4096
#define K_DIM  256
#define NN     16384
#define KTOP   1638

// GEMM tiling
#define TR 128              // rows per tile
#define TC 128              // cols per tile
#define GEMM_THREADS 512
#define XS_STRIDE 132       // floats; 132*4=528=33*16 -> LDS.128 16B-aligned
#define OS_STRIDE 129       // 129 % 32 == 1 -> conflict-free column stores
#define SLOTS 64            // per-column CSC capacity (binomial(256,0.1) max ~48)

#define PP_OFF   (K_DIM * XS_STRIDE)            // float index of pair tile
#define SCNT_OFF (PP_OFF + SLOTS * TC * 2)      // float index of counts
#define GEMM_SMEM ((SCNT_OFF + TC) * 4)         // 201216 B

// ---------------------------------------------------------------------------
// Scratch: CSC of W, [slot][n] layout (coalesced build writes AND gemm loads)
// pair = (w, k-as-float-bits). Slots >= cnt are zero-filled => inert in FMA.
// ---------------------------------------------------------------------------
__device__ float2 g_pairT[(size_t)SLOTS * NN];   // 8.4 MB
__device__ int    g_cnt[NN];

// ---------------------------------------------------------------------------
// Kernel 0: zero the pair scratch (makes padded slots inert every replay).
// ---------------------------------------------------------------------------
__global__ void __launch_bounds__(256) zero_pairs_kernel() {
    const size_t i = (size_t)blockIdx.x * 256 + threadIdx.x;   // float4 units
    ((float4*)g_pairT)[i] = make_float4(0.f, 0.f, 0.f, 0.f);
}

// ---------------------------------------------------------------------------
// Kernel 1: build CSC. One thread per column; W reads and g_pairT writes are
// both coalesced across adjacent n. Zero weights dropped (sum unchanged).
// ---------------------------------------------------------------------------
__global__ void __launch_bounds__(128) build_pack_kernel(const float* __restrict__ W) {
    const int n = blockIdx.x * blockDim.x + threadIdx.x;
    if (n >= NN) return;
    int c = 0;
#pragma unroll 8
    for (int k = 0; k < K_DIM; ++k) {
        const float w = W[(size_t)k * NN + n];
        if (w != 0.0f) {
            if (c < SLOTS) g_pairT[(size_t)c * NN + n] = make_float2(w, __int_as_float(k));
            ++c;
        }
    }
    g_cnt[n] = (c < SLOTS) ? c : SLOTS;
}

// ---------------------------------------------------------------------------
// Kernel 2: sparse GEMM  out = relu(x @ W + bias), dense output.
// Tile 128 rows x 128 cols, 512 threads / 16 warps; warp owns 8 columns,
// lane owns 4 consecutive rows (float4 from smem x-tile).
// Column pair lists staged in SMEM; in-loop pair reads are warp-uniform
// LDS.64 broadcasts (no shfl, no in-loop LDG). 8 column accumulators are
// kept in registers; the output staging buffer overlays the x-tile.
// ---------------------------------------------------------------------------
__global__ void __launch_bounds__(GEMM_THREADS, 1) gemm_kernel(
    const float* __restrict__ x,
    const float* __restrict__ bias,
    float* __restrict__ out)
{
    extern __shared__ float sm[];
    float*  xs    = sm;                          // [K_DIM][XS_STRIDE]
    float2* ppair = (float2*)(sm + PP_OFF);      // [SLOTS][TC]
    int*    scnt  = (int*)(sm + SCNT_OFF);       // [TC]

    const int row0 = blockIdx.y * TR;
    const int col0 = blockIdx.x * TC;
    const int tid  = threadIdx.x;

    // fill x tile transposed: xs[k][r]  (gmem coalesced)
    for (int u = tid; u < TR * K_DIM; u += GEMM_THREADS) {
        const int r = u >> 8;                // 0..127
        const int k = u & 255;               // 0..255
        xs[k * XS_STRIDE + r] = x[(size_t)(row0 + r) * K_DIM + k];
    }
    // fill pair tile: ppair[s][c] <- g_pairT[s][col0+c]  (LDG.64 coalesced)
    for (int u = tid; u < SLOTS * TC; u += GEMM_THREADS) {
        const int s = u >> 7;                // slot
        const int c = u & 127;               // col in tile
        ppair[s * TC + c] = g_pairT[(size_t)s * NN + col0 + c];
    }
    if (tid < TC) scnt[tid] = g_cnt[col0 + tid];
    __syncthreads();

    const int warp  = tid >> 5;              // 0..15
    const int lane  = tid & 31;
    const int rbase = lane << 2;

    float4 acc[8];
#pragma unroll
    for (int cc = 0; cc < 8; ++cc) {
        const int c = (warp << 3) + cc;
        const int cnt = scnt[c];
        const float2* pp = ppair + c;
        float4 a = make_float4(0.f, 0.f, 0.f, 0.f);
        for (int j = 0; j < cnt; j += 8) {   // tail slots are zero => inert
#pragma unroll
            for (int u = 0; u < 8; ++u) {
                const float2 p = pp[(j + u) * TC];              // broadcast
                const int    k = __float_as_int(p.y);
                const float4 xv = *(const float4*)(xs + k * XS_STRIDE + rbase);
                a.x = fmaf(xv.x, p.x, a.x);
                a.y = fmaf(xv.y, p.x, a.y);
                a.z = fmaf(xv.z, p.x, a.z);
                a.w = fmaf(xv.w, p.x, a.w);
            }
        }
        const float b = __ldg(bias + col0 + c);
        a.x = fmaxf(a.x + b, 0.f);
        a.y = fmaxf(a.y + b, 0.f);
        a.z = fmaxf(a.z + b, 0.f);
        a.w = fmaxf(a.w + b, 0.f);
        acc[cc] = a;
    }
    __syncthreads();                         // xs reads done -> reuse as os

    float* os = sm;                          // [TR][OS_STRIDE], overlays xs
#pragma unroll
    for (int cc = 0; cc < 8; ++cc) {
        const int c = (warp << 3) + cc;
        os[(rbase + 0) * OS_STRIDE + c] = acc[cc].x;
        os[(rbase + 1) * OS_STRIDE + c] = acc[cc].y;
        os[(rbase + 2) * OS_STRIDE + c] = acc[cc].z;
        os[(rbase + 3) * OS_STRIDE + c] = acc[cc].w;
    }
    __syncthreads();

    // flush tile, scalar + coalesced (consecutive threads -> consecutive cols)
    for (int l = tid; l < TR * TC; l += GEMM_THREADS) {
        const int r = l >> 7;
        const int c = l & 127;
        out[(size_t)(row0 + r) * NN + col0 + c] = os[r * OS_STRIDE + c];
    }
}

// ---------------------------------------------------------------------------
// Kernel 3: per-row exact top-K (radix select on float bits; relu => all >= 0
// so uint compare is order-preserving). In-place on `out`.
// NO row cache: row is re-read from gmem each pass (L2-resident between
// passes). Static smem ~19KB -> 8 CTAs/SM instead of 2.
// ---------------------------------------------------------------------------
__global__ void __launch_bounds__(256) topk_kernel(float* __restrict__ out) {
    __shared__ int hist[4096];        // pass1: 8x256 warp-private; p2:2048; p3:4096
    __shared__ int eqix[512];
    __shared__ int chunksum[256];
    __shared__ int s_b1, s_b2, s_b3, s_krem, s_eqcnt;

    const int t = threadIdx.x;
    const int warp = t >> 5, lane = t & 31;
    float* rp = out + (size_t)blockIdx.x * NN;
    const uint4* rp4 = (const uint4*)rp;

    // ---- pass 1: bits [31:23], warp-private 256-bin hists ----
    for (int i = t; i < 2048; i += 256) hist[i] = 0;
    __syncthreads();
    {
        int* h1 = hist + warp * 256;
        int zc = 0;
        for (int i = t; i < NN / 4; i += 256) {
            const uint4 q = rp4[i];
            if (q.x) atomicAdd(&h1[q.x >> 23], 1); else ++zc;
            if (q.y) atomicAdd(&h1[q.y >> 23], 1); else ++zc;
            if (q.z) atomicAdd(&h1[q.z >> 23], 1); else ++zc;
            if (q.w) atomicAdd(&h1[q.w >> 23], 1); else ++zc;
        }
#pragma unroll
        for (int off = 16; off; off >>= 1) zc += __shfl_down_sync(0xffffffffu, zc, off);
        if (lane == 0 && zc) atomicAdd(&h1[0], zc);
    }
    __syncthreads();
    {
        int s = 0;
        for (int w = 0; w < 8; ++w) s += hist[w * 256 + t];
        chunksum[t] = s;
    }
    __syncthreads();
    if (t == 0) {
        int kr = KTOP, b = 255;
        for (;; --b) { const int h = chunksum[b]; if (h >= kr) break; kr -= h; }
        s_b1 = b; s_krem = kr;
    }
    __syncthreads();
    const unsigned int b1 = (unsigned int)s_b1;

    // ---- pass 2: bits [22:12] (2048 bins) among prefix matches ----
    for (int i = t; i < 2048; i += 256) hist[i] = 0;
    __syncthreads();
    for (int i = t; i < NN / 4; i += 256) {
        const uint4 q = rp4[i];
        if ((q.x >> 23) == b1) atomicAdd(&hist[(q.x >> 12) & 2047], 1);
        if ((q.y >> 23) == b1) atomicAdd(&hist[(q.y >> 12) & 2047], 1);
        if ((q.z >> 23) == b1) atomicAdd(&hist[(q.z >> 12) & 2047], 1);
        if ((q.w >> 23) == b1) atomicAdd(&hist[(q.w >> 12) & 2047], 1);
    }
    __syncthreads();
    { int s = 0; for (int k = 0; k < 8; ++k) s += hist[t * 8 + k]; chunksum[t] = s; }
    __syncthreads();
    if (t == 0) {
        int kr = s_krem, c = 255;
        for (;; --c) { const int h = chunksum[c]; if (h >= kr) break; kr -= h; }
        int b = c * 8 + 7;
        for (;; --b) { const int h = hist[b]; if (h >= kr) break; kr -= h; }
        s_b2 = b; s_krem = kr;
    }
    __syncthreads();
    const unsigned int pfx2 = (b1 << 11) | (unsigned int)s_b2;

    // ---- pass 3: bits [11:0] (4096 bins) ----
    for (int i = t; i < 4096; i += 256) hist[i] = 0;
    __syncthreads();
    for (int i = t; i < NN / 4; i += 256) {
        const uint4 q = rp4[i];
        if ((q.x >> 12) == pfx2) atomicAdd(&hist[q.x & 4095], 1);
        if ((q.y >> 12) == pfx2) atomicAdd(&hist[q.y & 4095], 1);
        if ((q.z >> 12) == pfx2) atomicAdd(&hist[q.z & 4095], 1);
        if ((q.w >> 12) == pfx2) atomicAdd(&hist[q.w & 4095], 1);
    }
    __syncthreads();
    { int s = 0; for (int k = 0; k < 16; ++k) s += hist[t * 16 + k]; chunksum[t] = s; }
    __syncthreads();
    if (t == 0) {
        int kr = s_krem, c = 255;
        for (;; --c) { const int h = chunksum[c]; if (h >= kr) break; kr -= h; }
        int b = c * 16 + 15;
        for (;; --b) { const int h = hist[b]; if (h >= kr) break; kr -= h; }
        s_b3 = b; s_krem = kr;        // kr = # of elements == threshold to KEEP
        s_eqcnt = 0;
    }
    __syncthreads();

    const unsigned int tbits = (pfx2 << 12) | (unsigned int)s_b3;
    const int need = s_krem;
    const int m    = hist[s_b3];
    const bool keep_all_eq = (need >= m) || (m > 512);

    // exact tie ranking (lowest indices first) — rare path
    if (tbits != 0u && !keep_all_eq) {
        const unsigned int* rpu = (const unsigned int*)rp;
        for (int i = t; i < NN; i += 256)
            if (rpu[i] == tbits) { const int p = atomicAdd(&s_eqcnt, 1); eqix[p] = i; }
        __syncthreads();
    }

    // write masked row back (read-modify-write, elementwise in place)
    uint4* wp4 = (uint4*)rp;
    for (int i = t; i < NN / 4; i += 256) {
        uint4 q = rp4[i];
        const int base = i * 4;
#pragma unroll
        for (int c = 0; c < 4; ++c) {
            unsigned int u = (c == 0) ? q.x : (c == 1) ? q.y : (c == 2) ? q.z : q.w;
            unsigned int r = 0u;
            if (u > tbits) {
                r = u;
            } else if (u == tbits && tbits != 0u) {
                if (keep_all_eq) {
                    r = u;
                } else {
                    int rank = 0;
                    for (int qq = 0; qq < m; ++qq) rank += (eqix[qq] < base + c);
                    if (rank < need) r = u;
                }
            }
            if (c == 0) q.x = r; else if (c == 1) q.y = r; else if (c == 2) q.z = r; else q.w = r;
        }
        wp4[i] = q;
    }
}

// ---------------------------------------------------------------------------
// Launch
// ---------------------------------------------------------------------------
extern "C" void kernel_launch(void* const* d_in, const int* in_sizes, int n_in,
                              void* d_out, int out_size)
{
    const float* x = nullptr;
    const float* W = nullptr;
    const float* bias = nullptr;
    for (int i = 0; i < n_in; ++i) {
        if (in_sizes[i] == M_ROWS * K_DIM)      x = (const float*)d_in[i];
        else if (in_sizes[i] == K_DIM * NN)     W = (const float*)d_in[i];
        else if (in_sizes[i] == NN)             bias = (const float*)d_in[i];
    }
    float* out = (float*)d_out;

    cudaFuncSetAttribute(gemm_kernel, cudaFuncAttributeMaxDynamicSharedMemorySize, GEMM_SMEM);

    // zero pair scratch: SLOTS*NN float2 = SLOTS*NN/2 float4
    zero_pairs_kernel<<<(SLOTS * NN / 2) / 256, 256>>>();
    build_pack_kernel<<<NN / 128, 128>>>(W);

    dim3 ggrid(NN / TC, M_ROWS / TR);        // 128 x 32 = 4096 tiles
    gemm_kernel<<<ggrid, GEMM_THREADS, GEMM_SMEM>>>(x, bias, out);

    topk_kernel<<<M_ROWS, 256>>>(out);
}